// round 15
// baseline (speedup 1.0000x reference)
#include <cuda_runtime.h>
#include <math.h>
#include <stdint.h>

// ---------------- problem dims ----------------
#define TT    10
#define BBs   4
#define CCh   256
#define NP    256          // H*W = 16*16
#define TRR   40           // STEP*RATIO
#define HIDD  1024
#define EPSL  1e-5f

#define BCN   (BBs*CCh*NP)     // 262144 = 2^18
#define BHN   (BBs*HIDD*NP)    // 1048576
#define S_TBCN  (TT*BCN)       // 2,621,440
#define S_TRBCN (TRR*BBs*CCh*NP) // 10,485,760

// ---------------- scratch ----------------
__device__ float g_bufA[S_TRBCN];      // qkv gemm out / fc1 out
__device__ float g_bufB[S_TRBCN];      // fc1 spikes
__device__ float g_spk1[3*S_TRBCN];    // conv1 spikes, [br][u][b][c][n]
__device__ float g_spk2[3*S_TBCN];     // branch spikes, [br][t][b][c][n]
__device__ float g_y[S_TBCN];
__device__ float g_o[S_TBCN];
__device__ float g_h[S_TBCN];
__device__ float g_ktv[TT*BBs*16*256];
__device__ float g_wqkv[3*CCh*CCh];
__device__ float g_scale[2560];
__device__ float g_shift[2560];
__device__ float g_t1s[TRR], g_t1h[TRR];
__device__ float g_t2s[TT],  g_t2h[TT];

// scale/shift slice offsets
#define SC_QKV  0
#define SC_PROJ 768
#define SC_FC1  1024
#define SC_FC2  2048

// ---------------- cp.async helpers ----------------
__device__ __forceinline__ void cpasync4(uint32_t saddr, const float* g) {
    asm volatile("cp.async.ca.shared.global [%0], [%1], 4;" :: "r"(saddr), "l"(g));
}
#define CP_COMMIT() asm volatile("cp.async.commit_group;" ::: "memory")
#define CP_WAIT0()  asm volatile("cp.async.wait_group 0;" ::: "memory")

// ---------------- merged prep: wqkv concat + ALL BN folds in one launch ----------------
__device__ __forceinline__ void fold_one(const float* __restrict__ bnp, const float* __restrict__ bias,
                                         int cnum, int i, float* __restrict__ s_, float* __restrict__ h_)
{
    if (i >= cnum) return;
    float g  = bnp[i];
    float be = bnp[cnum + i];
    float m  = bnp[2*cnum + i];
    float v  = bnp[3*cnum + i];
    float s  = g / sqrtf(v + EPSL);
    float sh = be - m * s;
    if (bias) sh += bias[i] * s;
    s_[i] = s;
    h_[i] = sh;
}

__global__ void prep_all_kernel(
    const float* __restrict__ qw, const float* __restrict__ kw, const float* __restrict__ vw,
    float* __restrict__ wqkv,
    const float* __restrict__ qbn, const float* __restrict__ kbn, const float* __restrict__ vbn,
    const float* __restrict__ projbn,
    const float* __restrict__ fc1bn, const float* __restrict__ fc1b,
    const float* __restrict__ fc2bn, const float* __restrict__ fc2b,
    const float* __restrict__ t1bn, const float* __restrict__ t2bn,
    float* __restrict__ scal, float* __restrict__ shif,
    float* __restrict__ t1s, float* __restrict__ t1h,
    float* __restrict__ t2s, float* __restrict__ t2h)
{
    int bx = blockIdx.x, tid = threadIdx.x;
    if (bx < 768) {
        int i = bx * 256 + tid;
        const int n = CCh * CCh;
        float v = (i < n) ? qw[i] : (i < 2*n) ? kw[i - n] : vw[i - 2*n];
        wqkv[i] = v;
        return;
    }
    int job = bx - 768;
    switch (job) {
        case 0:  fold_one(qbn,    nullptr, 256,  tid, scal + SC_QKV,       shif + SC_QKV);       break;
        case 1:  fold_one(kbn,    nullptr, 256,  tid, scal + SC_QKV + 256, shif + SC_QKV + 256); break;
        case 2:  fold_one(vbn,    nullptr, 256,  tid, scal + SC_QKV + 512, shif + SC_QKV + 512); break;
        case 3:  fold_one(projbn, nullptr, 256,  tid, scal + SC_PROJ,      shif + SC_PROJ);      break;
        case 4: case 5: case 6: case 7:
                 fold_one(fc1bn,  fc1b,    1024, (job - 4) * 256 + tid, scal + SC_FC1, shif + SC_FC1); break;
        case 8:  fold_one(fc2bn,  fc2b,    256,  tid, scal + SC_FC2,       shif + SC_FC2);       break;
        case 9:  fold_one(t1bn,   nullptr, TRR,  tid, t1s, t1h); break;
        case 10: fold_one(t2bn,   nullptr, TT,   tid, t2s, t2h); break;
    }
}

// ---------------- batched GEMM + BN epilogue ----------------
// CTA tile 128(o) x 128(n), BK=8, 256 threads, microtile 16x4.
#define APITCH 132
__global__ __launch_bounds__(256, 2)
void gemm_bn_kernel(const float* __restrict__ In, const float* __restrict__ Wm,
                    float* __restrict__ Out, int O, int K,
                    const float* __restrict__ scale, const float* __restrict__ shift)
{
    __shared__ __align__(16) float sA[2][8][APITCH];   // [buf][k][o] padded
    __shared__ __align__(16) float sB[2][8][128];      // [buf][k][n]
    int tb = blockIdx.z;
    int oBase = blockIdx.x * 128;
    int nBase = blockIdx.y * 128;
    const float* Bp = In + (size_t)tb * K * NP + nBase;
    float* Cp = Out + (size_t)tb * O * NP + nBase;
    int tid = threadIdx.x;
    int lane = tid & 31, warp = tid >> 5;

    int aro = tid >> 1, akq = (tid & 1) * 4;
    int bk  = tid >> 5, bn  = (tid & 31) * 4;

    const float* wp = &Wm[(size_t)(oBase + aro) * K + akq];
    const float* bp = &Bp[(size_t)bk * NP + bn];

    float4 av = *(const float4*)wp;
    float4 bv = *(const float4*)bp;
    sA[0][akq + 0][aro] = av.x; sA[0][akq + 1][aro] = av.y;
    sA[0][akq + 2][aro] = av.z; sA[0][akq + 3][aro] = av.w;
    *(float4*)&sB[0][bk][bn] = bv;
    __syncthreads();

    float acc[16][4];
#pragma unroll
    for (int i = 0; i < 16; i++)
#pragma unroll
        for (int j = 0; j < 4; j++) acc[i][j] = 0.f;

    int nk = K >> 3;
    for (int kt = 0; kt < nk; kt++) {
        int cur = kt & 1;
        if (kt + 1 < nk) {
            av = *(const float4*)(wp + (kt + 1) * 8);
            bv = *(const float4*)(bp + (size_t)(kt + 1) * 8 * NP);
        }
#pragma unroll
        for (int kk = 0; kk < 8; kk++) {
            float4 b  = *(const float4*)&sB[cur][kk][bn];
            float4 a0 = *(const float4*)&sA[cur][kk][warp * 16 + 0];
            float4 a1 = *(const float4*)&sA[cur][kk][warp * 16 + 4];
            float4 a2 = *(const float4*)&sA[cur][kk][warp * 16 + 8];
            float4 a3 = *(const float4*)&sA[cur][kk][warp * 16 + 12];
#define ROW(i, s) \
            acc[i][0] += (s) * b.x; acc[i][1] += (s) * b.y; \
            acc[i][2] += (s) * b.z; acc[i][3] += (s) * b.w;
            ROW(0, a0.x)  ROW(1, a0.y)  ROW(2, a0.z)  ROW(3, a0.w)
            ROW(4, a1.x)  ROW(5, a1.y)  ROW(6, a1.z)  ROW(7, a1.w)
            ROW(8, a2.x)  ROW(9, a2.y)  ROW(10, a2.z) ROW(11, a2.w)
            ROW(12, a3.x) ROW(13, a3.y) ROW(14, a3.z) ROW(15, a3.w)
#undef ROW
        }
        if (kt + 1 < nk) {
            int nxt = cur ^ 1;
            sA[nxt][akq + 0][aro] = av.x; sA[nxt][akq + 1][aro] = av.y;
            sA[nxt][akq + 2][aro] = av.z; sA[nxt][akq + 3][aro] = av.w;
            *(float4*)&sB[nxt][bk][bn] = bv;
        }
        __syncthreads();
    }

#pragma unroll
    for (int i = 0; i < 16; i++) {
        int o = oBase + warp * 16 + i;
        float sc = scale[o], sh = shift[o];
        float4 r;
        r.x = acc[i][0] * sc + sh; r.y = acc[i][1] * sc + sh;
        r.z = acc[i][2] * sc + sh; r.w = acc[i][3] * sc + sh;
        *(float4*)&Cp[(size_t)o * NP + lane * 4] = r;
    }
}

// ---------------- TIM conv1 + BN + fused LIF1, pixel-pair microtile, hoisted indexing ----
__global__ __launch_bounds__(256)
void tim_conv1_kernel(const float* __restrict__ in, const float* __restrict__ wup,
                      const float* __restrict__ sc, const float* __restrict__ sh,
                      float* __restrict__ out)
{
    __shared__ __align__(16) float sW[2][1080];
    __shared__ float sIn[2][3 * 342];     // [dc][18 rows x pitch 19]
    __shared__ float sSc[40], sSh[40];
    int c  = blockIdx.x;
    int b  = blockIdx.y;
    int br = blockIdx.z;
    int tid = threadIdx.x;
    const float* inb = in + ((size_t)b * 768 + br * 256) * NP;

    if (tid < 40) { sSc[tid] = sc[tid]; sSh[tid] = sh[tid]; }

    int giOff[4], siOff[4];
#pragma unroll
    for (int j = 0; j < 4; j++) {
        int i = tid + j * 256;
        siOff[j] = -1; giOff[j] = -1;
        if (i < 972) {
            int dc = i / 324, rem = i % 324;
            int hh = rem / 18, ww = rem % 18;
            int ci = c + dc - 1;
            int hy = hh - 1, wx = ww - 1;
            siOff[j] = dc * 342 + hh * 19 + ww;
            if (ci >= 0 && ci < CCh && hy >= 0 && hy < 16 && wx >= 0 && wx < 16)
                giOff[j] = ci * NP + hy * 16 + wx;
        }
    }
    int gwOff[5], swOff[5];
#pragma unroll
    for (int j = 0; j < 5; j++) {
        int i = tid + j * 256;
        swOff[j] = -1; gwOff[j] = 0;
        if (i < 1080) {
            int u = i % 40, tap = i / 40;
            int pos = ((u & 3) >> 1) * 20 + (u >> 2) * 2 + (u & 1);
            swOff[j] = tap * 40 + pos;
            gwOff[j] = u * 270 + tap;
        }
    }

    {
        float ip[4], wpre[5];
#pragma unroll
        for (int j = 0; j < 4; j++) ip[j] = (giOff[j] >= 0) ? inb[giOff[j]] : 0.f;
#pragma unroll
        for (int j = 0; j < 5; j++) wpre[j] = (swOff[j] >= 0) ? wup[gwOff[j]] : 0.f;
#pragma unroll
        for (int j = 0; j < 4; j++) if (siOff[j] >= 0) sIn[0][siOff[j]] = ip[j];
#pragma unroll
        for (int j = 0; j < 5; j++) if (swOff[j] >= 0) sW[0][swOff[j]] = wpre[j];
    }
    __syncthreads();

    int uh = tid >> 7;
    int pp = tid & 127;
    int h = pp >> 3, w0 = (pp & 7) * 2;

    float acc[2][20];
#pragma unroll
    for (int px = 0; px < 2; px++)
#pragma unroll
        for (int j = 0; j < 20; j++) acc[px][j] = 0.f;

#pragma unroll 1
    for (int t = 0; t < 10; t++) {
        int cur = t & 1;
        float ip[4], wpre[5];
        if (t < 9) {
            const float* inb2 = inb + (size_t)(t + 1) * (BBs * 768 * NP);
            int wofs = (t + 1) * 27;
#pragma unroll
            for (int j = 0; j < 4; j++) ip[j] = (giOff[j] >= 0) ? inb2[giOff[j]] : 0.f;
#pragma unroll
            for (int j = 0; j < 5; j++) wpre[j] = (swOff[j] >= 0) ? wup[gwOff[j] + wofs] : 0.f;
        }

#pragma unroll
        for (int dc = 0; dc < 3; dc++) {
#pragma unroll
            for (int dh = 0; dh < 3; dh++) {
                const float* rowp = &sIn[cur][dc * 342 + (h + dh) * 19 + w0];
                float iv[4] = {rowp[0], rowp[1], rowp[2], rowp[3]};
#pragma unroll
                for (int dw = 0; dw < 3; dw++) {
                    float v0 = iv[dw], v1 = iv[dw + 1];
                    const float4* wq = (const float4*)&sW[cur][((dc * 3 + dh) * 3 + dw) * 40 + uh * 20];
#pragma unroll
                    for (int j = 0; j < 5; j++) {
                        float4 w4 = wq[j];
                        acc[0][4*j + 0] += v0 * w4.x; acc[1][4*j + 0] += v1 * w4.x;
                        acc[0][4*j + 1] += v0 * w4.y; acc[1][4*j + 1] += v1 * w4.y;
                        acc[0][4*j + 2] += v0 * w4.z; acc[1][4*j + 2] += v1 * w4.z;
                        acc[0][4*j + 3] += v0 * w4.w; acc[1][4*j + 3] += v1 * w4.w;
                    }
                }
            }
        }

        if (t < 9) {
            int nxt = cur ^ 1;
            __syncthreads();
#pragma unroll
            for (int j = 0; j < 4; j++) if (siOff[j] >= 0) sIn[nxt][siOff[j]] = ip[j];
#pragma unroll
            for (int j = 0; j < 5; j++) if (swOff[j] >= 0) sW[nxt][swOff[j]] = wpre[j];
        }
        __syncthreads();
    }

    size_t ob = ((size_t)(br * 40) * BBs + b) * CCh * NP + (size_t)c * NP + 2 * pp;
#pragma unroll
    for (int r01 = 0; r01 < 2; r01++) {
        int r = 2 * uh + r01;
        float mem0 = 0.f, mem1 = 0.f;
#pragma unroll
        for (int s = 0; s < 10; s++) {
            int u = 4 * s + r;
            int j = 2 * s + r01;
            float y0 = acc[0][j] * sSc[u] + sSh[u];
            float y1 = acc[1][j] * sSc[u] + sSh[u];
            mem0 = mem0 + (y0 - mem0) * 0.5f;
            mem1 = mem1 + (y1 - mem1) * 0.5f;
            float s0 = ((mem0 - 1.0f) > 0.f) ? 1.f : 0.f;
            float s1 = ((mem1 - 1.0f) > 0.f) ? 1.f : 0.f;
            float2 o2; o2.x = s0; o2.y = s1;
            *(float2*)&out[ob + (size_t)u * (BBs * CCh * NP)] = o2;
            if (s0 != 0.f) mem0 = 0.f;
            if (s1 != 0.f) mem1 = 0.f;
        }
    }
}

// ---------------- TIM conv2 (grouped) + BN + fused LIF2 ----------------
// pixel-pair microtile (128 compute threads), float4 weight rows, cp.async staging.
// plane pitch 20 (even) -> aligned float2 input loads.
#define C2P 20
#define C2PL (18 * C2P)   // 360
__global__ __launch_bounds__(256)
void tim_conv2_kernel(const float* __restrict__ sp, const float* __restrict__ wdn,
                      const float* __restrict__ sc, const float* __restrict__ sh,
                      float* __restrict__ out)
{
    __shared__ __align__(16) float4 sW4[360];      // [((t*4+r)*3+dc)*3+dh] = {w0,w1,w2,0}
    __shared__ float sIn[2][12 * C2PL];
    __shared__ float sT2s[TT], sT2h[TT];
    int c  = blockIdx.x;
    int z  = blockIdx.y;
    int b  = z & 3;
    int br = z >> 2;
    int tid = threadIdx.x;

    // zero weight pad + both input buffers (halo zeros are t-invariant)
    for (int i = tid; i < 360; i += 256) sW4[i] = make_float4(0.f, 0.f, 0.f, 0.f);
    for (int i = tid; i < 12 * C2PL; i += 256) { sIn[0][i] = 0.f; sIn[1][i] = 0.f; }
    if (tid < TT) { sT2s[tid] = sc[tid]; sT2h[tid] = sh[tid]; }
    __syncthreads();
    for (int i = tid; i < 1080; i += 256)
        ((float*)sW4)[(i / 3) * 4 + (i % 3)] = wdn[i];

    // hoisted staging descriptors (t-invariant; gmem advances by t*stride)
    int sOff[16], gOff[16];
#pragma unroll
    for (int j = 0; j < 16; j++) {
        int i = tid + j * 256;
        sOff[j] = 0; gOff[j] = -1;
        if (i < 3888) {
            int pl = i / 324, rem = i % 324;
            int hh = rem / 18, ww = rem % 18;
            int r = pl / 3, dc = pl % 3;
            int ci = c + dc - 1;
            int hy = hh - 1, wx = ww - 1;
            sOff[j] = pl * C2PL + hh * C2P + ww;
            if (ci >= 0 && ci < CCh && hy >= 0 && hy < 16 && wx >= 0 && wx < 16)
                gOff[j] = (((br * 40 + r) * BBs + b) * CCh + ci) * NP + hy * 16 + wx;
        }
    }
    uint32_t sbase0 = (uint32_t)__cvta_generic_to_shared(&sIn[0][0]);
    uint32_t sbase1 = (uint32_t)__cvta_generic_to_shared(&sIn[1][0]);

    // stage t=0 into buf0
#pragma unroll
    for (int j = 0; j < 16; j++)
        if (gOff[j] >= 0) cpasync4(sbase0 + sOff[j] * 4, sp + gOff[j]);
    CP_COMMIT();
    CP_WAIT0();
    __syncthreads();

    int pp = tid;                  // 0..127 compute a pixel pair
    int h = pp >> 3, w0 = (pp & 7) * 2;
    float mem0 = 0.f, mem1 = 0.f;
    size_t obase = (size_t)br * S_TBCN + ((size_t)b * CCh + c) * NP + h * 16 + w0;

#pragma unroll 1
    for (int t = 0; t < 10; t++) {
        int cur = t & 1;
        if (t < 9) {
            const float* spt = sp + (size_t)(t + 1) * (4 * BBs * CCh * NP);
            uint32_t sb = (cur ? sbase0 : sbase1);
#pragma unroll
            for (int j = 0; j < 16; j++)
                if (gOff[j] >= 0) cpasync4(sb + sOff[j] * 4, spt + gOff[j]);
            CP_COMMIT();
        }

        if (tid < 128) {
            float a0 = 0.f, a1 = 0.f;
            const float4* wrow = &sW4[t * 36];
#pragma unroll
            for (int r = 0; r < 4; r++) {
#pragma unroll
                for (int dc = 0; dc < 3; dc++) {
                    const float* pv = &sIn[cur][(r * 3 + dc) * C2PL + h * C2P + w0];
                    const float4* wq = &wrow[(r * 3 + dc) * 3];
#pragma unroll
                    for (int dh = 0; dh < 3; dh++) {
                        float4 wv = wq[dh];
                        float2 i01 = *(const float2*)&pv[dh * C2P];
                        float2 i23 = *(const float2*)&pv[dh * C2P + 2];
                        a0 += i01.x * wv.x; a0 += i01.y * wv.y; a0 += i23.x * wv.z;
                        a1 += i01.y * wv.x; a1 += i23.x * wv.y; a1 += i23.y * wv.z;
                    }
                }
            }
            float y0 = a0 * sT2s[t] + sT2h[t];
            float y1 = a1 * sT2s[t] + sT2h[t];
            mem0 = mem0 + (y0 - mem0) * 0.5f;
            mem1 = mem1 + (y1 - mem1) * 0.5f;
            float s0 = ((mem0 - 1.0f) > 0.f) ? 1.f : 0.f;
            float s1 = ((mem1 - 1.0f) > 0.f) ? 1.f : 0.f;
            float2 o2; o2.x = s0; o2.y = s1;
            *(float2*)&out[obase + (size_t)t * BCN] = o2;
            if (s0 != 0.f) mem0 = 0.f;
            if (s1 != 0.f) mem1 = 0.f;
        }

        if (t < 9) {
            CP_WAIT0();
            __syncthreads();
        }
    }
}

// ---------------- LIF variants ----------------
__global__ void lif_kernel(const float* __restrict__ in, float* __restrict__ out,
                           int nChains, int stride, float vth)
{
    int i = blockIdx.x * blockDim.x + threadIdx.x;
    if (i >= nChains) return;
    float mem = 0.f;
    int p = i;
#pragma unroll
    for (int s = 0; s < 10; s++, p += stride) {
        float x = in[p];
        mem = mem + (x - mem) * 0.5f;
        float spk = ((mem - vth) > 0.f) ? 1.f : 0.f;
        out[p] = spk;
        if (spk != 0.f) mem = 0.f;
    }
}

__global__ void lif_resid_kernel(const float* __restrict__ in, const float* __restrict__ res,
                                 float* __restrict__ out, int nChains, int stride, float vth)
{
    int i = blockIdx.x * blockDim.x + threadIdx.x;
    if (i >= nChains) return;
    float mem = 0.f;
    int p = i;
#pragma unroll
    for (int s = 0; s < 10; s++, p += stride) {
        float x = in[p];
        mem = mem + (x - mem) * 0.5f;
        float spk = ((mem - vth) > 0.f) ? 1.f : 0.f;
        out[p] = res[p] + spk;
        if (spk != 0.f) mem = 0.f;
    }
}

// ---------------- KtV: per (t,b,head): 16x16 Gram over N ----------------
__global__ void ktv_kernel(const float* __restrict__ ks, const float* __restrict__ vs,
                           float* __restrict__ ktv)
{
    __shared__ float kT[16 * 257];
    __shared__ float vT[16 * 257];
    int tbh = blockIdx.x;
    int hh = tbh & 15;
    int tb = tbh >> 4;
    size_t base = ((size_t)tb * CCh + hh * 16) * NP;
    int tid = threadIdx.x;
    for (int i = tid; i < 16 * 256; i += 256) {
        int r = i >> 8, n = i & 255;
        kT[r * 257 + n] = ks[base + (size_t)r * NP + n];
        vT[r * 257 + n] = vs[base + (size_t)r * NP + n];
    }
    __syncthreads();
    int dd = tid >> 4, de = tid & 15;
    const float* kr = &kT[dd * 257];
    const float* vr = &vT[de * 257];
    float acc = 0.f;
#pragma unroll 8
    for (int n = 0; n < 256; n++) acc += kr[n] * vr[n];
    ktv[(size_t)tbh * 256 + dd * 16 + de] = acc;
}

// ---------------- attn out: o = 0.25 * Q (KtV) ----------------
__global__ void attn_o_kernel(const float* __restrict__ qs, const float* __restrict__ ktv,
                              float* __restrict__ o)
{
    __shared__ float sK[256];
    int tbh = blockIdx.x;
    int hh = tbh & 15;
    int tb = tbh >> 4;
    int tid = threadIdx.x;
    sK[tid] = ktv[(size_t)tbh * 256 + tid];
    __syncthreads();
    size_t base = ((size_t)tb * CCh + hh * 16) * NP + tid;
    float q[16];
#pragma unroll
    for (int d = 0; d < 16; d++) q[d] = qs[base + (size_t)d * NP];
#pragma unroll
    for (int dp = 0; dp < 16; dp++) {
        float acc = 0.f;
#pragma unroll
        for (int d = 0; d < 16; d++) acc += q[d] * sK[d * 16 + dp];
        o[base + (size_t)dp * NP] = acc * 0.25f;
    }
}

// ---------------- orchestration ----------------
extern "C" void kernel_launch(void* const* d_in, const int* in_sizes, int n_in,
                              void* d_out, int out_size)
{
    (void)in_sizes; (void)n_in; (void)out_size;
    const float* x        = (const float*)d_in[0];
    const float* q_w      = (const float*)d_in[1];
    const float* q_bn     = (const float*)d_in[2];
    const float* k_w      = (const float*)d_in[3];
    const float* k_bn     = (const float*)d_in[4];
    const float* v_w      = (const float*)d_in[5];
    const float* v_bn     = (const float*)d_in[6];
    const float* proj_w   = (const float*)d_in[7];
    const float* proj_bn  = (const float*)d_in[8];
    const float* tim_up_w = (const float*)d_in[9];
    const float* tim_bn1  = (const float*)d_in[10];
    const float* tim_dn_w = (const float*)d_in[11];
    const float* tim_bn2  = (const float*)d_in[12];
    const float* fc1_w    = (const float*)d_in[13];
    const float* fc1_b    = (const float*)d_in[14];
    const float* fc1_bn   = (const float*)d_in[15];
    const float* fc2_w    = (const float*)d_in[16];
    const float* fc2_b    = (const float*)d_in[17];
    const float* fc2_bn   = (const float*)d_in[18];
    float* outp = (float*)d_out;

    float *bufA, *bufB, *spk1, *spk2, *ybuf, *obuf, *hbuf, *ktvb, *wqkv;
    float *scal, *shif, *t1s, *t1h, *t2s, *t2h;
    cudaGetSymbolAddress((void**)&bufA, g_bufA);
    cudaGetSymbolAddress((void**)&bufB, g_bufB);
    cudaGetSymbolAddress((void**)&spk1, g_spk1);
    cudaGetSymbolAddress((void**)&spk2, g_spk2);
    cudaGetSymbolAddress((void**)&ybuf, g_y);
    cudaGetSymbolAddress((void**)&obuf, g_o);
    cudaGetSymbolAddress((void**)&hbuf, g_h);
    cudaGetSymbolAddress((void**)&ktvb, g_ktv);
    cudaGetSymbolAddress((void**)&wqkv, g_wqkv);
    cudaGetSymbolAddress((void**)&scal, g_scale);
    cudaGetSymbolAddress((void**)&shif, g_shift);
    cudaGetSymbolAddress((void**)&t1s,  g_t1s);
    cudaGetSymbolAddress((void**)&t1h,  g_t1h);
    cudaGetSymbolAddress((void**)&t2s,  g_t2s);
    cudaGetSymbolAddress((void**)&t2h,  g_t2h);

    // all setup in one launch: wqkv concat + every BN fold
    prep_all_kernel<<<779, 256>>>(q_w, k_w, v_w, wqkv,
                                  q_bn, k_bn, v_bn, proj_bn,
                                  fc1_bn, fc1_b, fc2_bn, fc2_b,
                                  tim_bn1, tim_bn2,
                                  scal, shif, t1s, t1h, t2s, t2h);

    // merged q/k/v GEMM: Out (tb, 768, n)
    gemm_bn_kernel<<<dim3(6, 2, TT*BBs), 256>>>(x, wqkv, bufA, 768, CCh,
                                                scal + SC_QKV, shif + SC_QKV);

    // TIM: conv1+BN+LIF1 (all branches), conv2+BN+LIF2 fused
    tim_conv1_kernel<<<dim3(CCh, BBs, 3), 256>>>(bufA, tim_up_w, t1s, t1h, spk1);
    tim_conv2_kernel<<<dim3(CCh, 12), 256>>>(spk1, tim_dn_w, t2s, t2h, spk2);

    // attention (linear, binary, exact): q=br0, k=br1, v=br2
    ktv_kernel<<<TT*BBs*16, 256>>>(spk2 + S_TBCN, spk2 + 2*S_TBCN, ktvb);
    attn_o_kernel<<<TT*BBs*16, 256>>>(spk2, ktvb, obuf);
    lif_kernel<<<(BCN + 255)/256, 256>>>(obuf, obuf, BCN, BCN, 0.5f);

    // projection + BN + lif; residual h = x + spikes
    gemm_bn_kernel<<<dim3(2, 2, TT*BBs), 256>>>(obuf, proj_w, ybuf, CCh, CCh,
                                                scal + SC_PROJ, shif + SC_PROJ);
    lif_resid_kernel<<<(BCN + 255)/256, 256>>>(ybuf, x, hbuf, BCN, BCN, 1.0f);

    // MLP
    gemm_bn_kernel<<<dim3(8, 2, TT*BBs), 256>>>(hbuf, fc1_w, bufA, HIDD, CCh,
                                                scal + SC_FC1, shif + SC_FC1);
    lif_kernel<<<(BHN + 255)/256, 256>>>(bufA, bufB, BHN, BHN, 1.0f);

    gemm_bn_kernel<<<dim3(2, 2, TT*BBs), 256>>>(bufB, fc2_w, ybuf, CCh, HIDD,
                                                scal + SC_FC2, shif + SC_FC2);
    lif_resid_kernel<<<(BCN + 255)/256, 256>>>(ybuf, hbuf, outp, BCN, BCN, 1.0f);
}

// round 16
// speedup vs baseline: 1.4967x; 1.4967x over previous
#include <cuda_runtime.h>
#include <math.h>

// ---------------- problem dims ----------------
#define TT    10
#define BBs   4
#define CCh   256
#define NP    256          // H*W = 16*16
#define TRR   40           // STEP*RATIO
#define HIDD  1024
#define EPSL  1e-5f

#define BCN   (BBs*CCh*NP)     // 262144 = 2^18
#define BHN   (BBs*HIDD*NP)    // 1048576
#define S_TBCN  (TT*BCN)       // 2,621,440
#define S_TRBCN (TRR*BBs*CCh*NP) // 10,485,760

// ---------------- scratch ----------------
__device__ float g_bufA[S_TRBCN];      // qkv gemm out / fc1 out
__device__ float g_bufB[S_TRBCN];      // fc1 spikes
__device__ float g_spk1[3*S_TRBCN];    // conv1 spikes, [br][u][b][c][n]
__device__ float g_spk2[3*S_TBCN];     // branch spikes, [br][t][b][c][n]
__device__ float g_y[S_TBCN];
__device__ float g_o[S_TBCN];
__device__ float g_h[S_TBCN];
__device__ float g_ktv[TT*BBs*16*256];
__device__ float g_wqkv[3*CCh*CCh];
__device__ float g_scale[2560];
__device__ float g_shift[2560];
__device__ float g_t1s[TRR], g_t1h[TRR];
__device__ float g_t2s[TT],  g_t2h[TT];

// scale/shift slice offsets
#define SC_QKV  0
#define SC_PROJ 768
#define SC_FC1  1024
#define SC_FC2  2048

// ---------------- merged prep: wqkv concat + ALL BN folds in one launch ----------------
__device__ __forceinline__ void fold_one(const float* __restrict__ bnp, const float* __restrict__ bias,
                                         int cnum, int i, float* __restrict__ s_, float* __restrict__ h_)
{
    if (i >= cnum) return;
    float g  = bnp[i];
    float be = bnp[cnum + i];
    float m  = bnp[2*cnum + i];
    float v  = bnp[3*cnum + i];
    float s  = g / sqrtf(v + EPSL);
    float sh = be - m * s;
    if (bias) sh += bias[i] * s;
    s_[i] = s;
    h_[i] = sh;
}

__global__ void prep_all_kernel(
    const float* __restrict__ qw, const float* __restrict__ kw, const float* __restrict__ vw,
    float* __restrict__ wqkv,
    const float* __restrict__ qbn, const float* __restrict__ kbn, const float* __restrict__ vbn,
    const float* __restrict__ projbn,
    const float* __restrict__ fc1bn, const float* __restrict__ fc1b,
    const float* __restrict__ fc2bn, const float* __restrict__ fc2b,
    const float* __restrict__ t1bn, const float* __restrict__ t2bn,
    float* __restrict__ scal, float* __restrict__ shif,
    float* __restrict__ t1s, float* __restrict__ t1h,
    float* __restrict__ t2s, float* __restrict__ t2h)
{
    int bx = blockIdx.x, tid = threadIdx.x;
    if (bx < 768) {
        int i = bx * 256 + tid;
        const int n = CCh * CCh;
        float v = (i < n) ? qw[i] : (i < 2*n) ? kw[i - n] : vw[i - 2*n];
        wqkv[i] = v;
        return;
    }
    int job = bx - 768;
    switch (job) {
        case 0:  fold_one(qbn,    nullptr, 256,  tid, scal + SC_QKV,       shif + SC_QKV);       break;
        case 1:  fold_one(kbn,    nullptr, 256,  tid, scal + SC_QKV + 256, shif + SC_QKV + 256); break;
        case 2:  fold_one(vbn,    nullptr, 256,  tid, scal + SC_QKV + 512, shif + SC_QKV + 512); break;
        case 3:  fold_one(projbn, nullptr, 256,  tid, scal + SC_PROJ,      shif + SC_PROJ);      break;
        case 4: case 5: case 6: case 7:
                 fold_one(fc1bn,  fc1b,    1024, (job - 4) * 256 + tid, scal + SC_FC1, shif + SC_FC1); break;
        case 8:  fold_one(fc2bn,  fc2b,    256,  tid, scal + SC_FC2,       shif + SC_FC2);       break;
        case 9:  fold_one(t1bn,   nullptr, TRR,  tid, t1s, t1h); break;
        case 10: fold_one(t2bn,   nullptr, TT,   tid, t2s, t2h); break;
    }
}

// ---------------- batched GEMM + BN epilogue ----------------
// CTA tile 128(o) x 128(n), BK=8, 256 threads, microtile 16x4.
#define APITCH 132
__global__ __launch_bounds__(256, 2)
void gemm_bn_kernel(const float* __restrict__ In, const float* __restrict__ Wm,
                    float* __restrict__ Out, int O, int K,
                    const float* __restrict__ scale, const float* __restrict__ shift)
{
    __shared__ __align__(16) float sA[2][8][APITCH];   // [buf][k][o] padded
    __shared__ __align__(16) float sB[2][8][128];      // [buf][k][n]
    int tb = blockIdx.z;
    int oBase = blockIdx.x * 128;
    int nBase = blockIdx.y * 128;
    const float* Bp = In + (size_t)tb * K * NP + nBase;
    float* Cp = Out + (size_t)tb * O * NP + nBase;
    int tid = threadIdx.x;
    int lane = tid & 31, warp = tid >> 5;

    int aro = tid >> 1, akq = (tid & 1) * 4;
    int bk  = tid >> 5, bn  = (tid & 31) * 4;

    const float* wp = &Wm[(size_t)(oBase + aro) * K + akq];
    const float* bp = &Bp[(size_t)bk * NP + bn];

    float4 av = *(const float4*)wp;
    float4 bv = *(const float4*)bp;
    sA[0][akq + 0][aro] = av.x; sA[0][akq + 1][aro] = av.y;
    sA[0][akq + 2][aro] = av.z; sA[0][akq + 3][aro] = av.w;
    *(float4*)&sB[0][bk][bn] = bv;
    __syncthreads();

    float acc[16][4];
#pragma unroll
    for (int i = 0; i < 16; i++)
#pragma unroll
        for (int j = 0; j < 4; j++) acc[i][j] = 0.f;

    int nk = K >> 3;
    for (int kt = 0; kt < nk; kt++) {
        int cur = kt & 1;
        if (kt + 1 < nk) {
            av = *(const float4*)(wp + (kt + 1) * 8);
            bv = *(const float4*)(bp + (size_t)(kt + 1) * 8 * NP);
        }
#pragma unroll
        for (int kk = 0; kk < 8; kk++) {
            float4 b  = *(const float4*)&sB[cur][kk][bn];
            float4 a0 = *(const float4*)&sA[cur][kk][warp * 16 + 0];
            float4 a1 = *(const float4*)&sA[cur][kk][warp * 16 + 4];
            float4 a2 = *(const float4*)&sA[cur][kk][warp * 16 + 8];
            float4 a3 = *(const float4*)&sA[cur][kk][warp * 16 + 12];
#define ROW(i, s) \
            acc[i][0] += (s) * b.x; acc[i][1] += (s) * b.y; \
            acc[i][2] += (s) * b.z; acc[i][3] += (s) * b.w;
            ROW(0, a0.x)  ROW(1, a0.y)  ROW(2, a0.z)  ROW(3, a0.w)
            ROW(4, a1.x)  ROW(5, a1.y)  ROW(6, a1.z)  ROW(7, a1.w)
            ROW(8, a2.x)  ROW(9, a2.y)  ROW(10, a2.z) ROW(11, a2.w)
            ROW(12, a3.x) ROW(13, a3.y) ROW(14, a3.z) ROW(15, a3.w)
#undef ROW
        }
        if (kt + 1 < nk) {
            int nxt = cur ^ 1;
            sA[nxt][akq + 0][aro] = av.x; sA[nxt][akq + 1][aro] = av.y;
            sA[nxt][akq + 2][aro] = av.z; sA[nxt][akq + 3][aro] = av.w;
            *(float4*)&sB[nxt][bk][bn] = bv;
        }
        __syncthreads();
    }

#pragma unroll
    for (int i = 0; i < 16; i++) {
        int o = oBase + warp * 16 + i;
        float sc = scale[o], sh = shift[o];
        float4 r;
        r.x = acc[i][0] * sc + sh; r.y = acc[i][1] * sc + sh;
        r.z = acc[i][2] * sc + sh; r.w = acc[i][3] * sc + sh;
        *(float4*)&Cp[(size_t)o * NP + lane * 4] = r;
    }
}

// ---------------- TIM conv1 + BN + fused LIF1, pixel-pair microtile, hoisted indexing ----
// Thread: uh = tid>>7 selects 20 u's = chains r in {2uh, 2uh+1}; pp = tid&127 selects pixel pair.
// Weight smem permuted: sW[tap*40 + pos(u)], pos(u) = (r>>1)*20 + s*2 + (r&1), u = 4s+r.
__global__ __launch_bounds__(256)
void tim_conv1_kernel(const float* __restrict__ in, const float* __restrict__ wup,
                      const float* __restrict__ sc, const float* __restrict__ sh,
                      float* __restrict__ out)
{
    __shared__ __align__(16) float sW[2][1080];
    __shared__ float sIn[2][3 * 342];     // [dc][18 rows x pitch 19]
    __shared__ float sSc[40], sSh[40];
    int c  = blockIdx.x;
    int b  = blockIdx.y;
    int br = blockIdx.z;
    int tid = threadIdx.x;
    const float* inb = in + ((size_t)b * 768 + br * 256) * NP;

    if (tid < 40) { sSc[tid] = sc[tid]; sSh[tid] = sh[tid]; }

    // ---- hoisted staging descriptors (t-invariant) ----
    int giOff[4], siOff[4];
#pragma unroll
    for (int j = 0; j < 4; j++) {
        int i = tid + j * 256;
        siOff[j] = -1; giOff[j] = -1;
        if (i < 972) {
            int dc = i / 324, rem = i % 324;
            int hh = rem / 18, ww = rem % 18;
            int ci = c + dc - 1;
            int hy = hh - 1, wx = ww - 1;
            siOff[j] = dc * 342 + hh * 19 + ww;
            if (ci >= 0 && ci < CCh && hy >= 0 && hy < 16 && wx >= 0 && wx < 16)
                giOff[j] = ci * NP + hy * 16 + wx;
        }
    }
    int gwOff[5], swOff[5];
#pragma unroll
    for (int j = 0; j < 5; j++) {
        int i = tid + j * 256;
        swOff[j] = -1; gwOff[j] = 0;
        if (i < 1080) {
            int u = i % 40, tap = i / 40;
            int pos = ((u & 3) >> 1) * 20 + (u >> 2) * 2 + (u & 1);
            swOff[j] = tap * 40 + pos;
            gwOff[j] = u * 270 + tap;
        }
    }

    // ---- prologue: stage t=0 ----
    {
        float ip[4], wpre[5];
#pragma unroll
        for (int j = 0; j < 4; j++) ip[j] = (giOff[j] >= 0) ? inb[giOff[j]] : 0.f;
#pragma unroll
        for (int j = 0; j < 5; j++) wpre[j] = (swOff[j] >= 0) ? wup[gwOff[j]] : 0.f;
#pragma unroll
        for (int j = 0; j < 4; j++) if (siOff[j] >= 0) sIn[0][siOff[j]] = ip[j];
#pragma unroll
        for (int j = 0; j < 5; j++) if (swOff[j] >= 0) sW[0][swOff[j]] = wpre[j];
    }
    __syncthreads();

    int uh = tid >> 7;            // 0/1: which 20-u half
    int pp = tid & 127;           // pixel pair index
    int h = pp >> 3, w0 = (pp & 7) * 2;

    float acc[2][20];
#pragma unroll
    for (int px = 0; px < 2; px++)
#pragma unroll
        for (int j = 0; j < 20; j++) acc[px][j] = 0.f;

#pragma unroll 1
    for (int t = 0; t < 10; t++) {
        int cur = t & 1;
        float ip[4], wpre[5];
        if (t < 9) {
            const float* inb2 = inb + (size_t)(t + 1) * (BBs * 768 * NP);
            int wofs = (t + 1) * 27;
#pragma unroll
            for (int j = 0; j < 4; j++) ip[j] = (giOff[j] >= 0) ? inb2[giOff[j]] : 0.f;
#pragma unroll
            for (int j = 0; j < 5; j++) wpre[j] = (swOff[j] >= 0) ? wup[gwOff[j] + wofs] : 0.f;
        }

        // ---- compute t ----
#pragma unroll
        for (int dc = 0; dc < 3; dc++) {
#pragma unroll
            for (int dh = 0; dh < 3; dh++) {
                const float* rowp = &sIn[cur][dc * 342 + (h + dh) * 19 + w0];
                float iv[4] = {rowp[0], rowp[1], rowp[2], rowp[3]};
#pragma unroll
                for (int dw = 0; dw < 3; dw++) {
                    float v0 = iv[dw], v1 = iv[dw + 1];
                    const float4* wq = (const float4*)&sW[cur][((dc * 3 + dh) * 3 + dw) * 40 + uh * 20];
#pragma unroll
                    for (int j = 0; j < 5; j++) {
                        float4 w4 = wq[j];
                        acc[0][4*j + 0] += v0 * w4.x; acc[1][4*j + 0] += v1 * w4.x;
                        acc[0][4*j + 1] += v0 * w4.y; acc[1][4*j + 1] += v1 * w4.y;
                        acc[0][4*j + 2] += v0 * w4.z; acc[1][4*j + 2] += v1 * w4.z;
                        acc[0][4*j + 3] += v0 * w4.w; acc[1][4*j + 3] += v1 * w4.w;
                    }
                }
            }
        }

        if (t < 9) {
            int nxt = cur ^ 1;
            __syncthreads();
#pragma unroll
            for (int j = 0; j < 4; j++) if (siOff[j] >= 0) sIn[nxt][siOff[j]] = ip[j];
#pragma unroll
            for (int j = 0; j < 5; j++) if (swOff[j] >= 0) sW[nxt][swOff[j]] = wpre[j];
        }
        __syncthreads();
    }

    // ---- BN + fused LIF1 epilogue (chains r = 2uh + r01) ----
    size_t ob = ((size_t)(br * 40) * BBs + b) * CCh * NP + (size_t)c * NP + 2 * pp;
#pragma unroll
    for (int r01 = 0; r01 < 2; r01++) {
        int r = 2 * uh + r01;
        float mem0 = 0.f, mem1 = 0.f;
#pragma unroll
        for (int s = 0; s < 10; s++) {
            int u = 4 * s + r;
            int j = 2 * s + r01;
            float y0 = acc[0][j] * sSc[u] + sSh[u];
            float y1 = acc[1][j] * sSc[u] + sSh[u];
            mem0 = mem0 + (y0 - mem0) * 0.5f;
            mem1 = mem1 + (y1 - mem1) * 0.5f;
            float s0 = ((mem0 - 1.0f) > 0.f) ? 1.f : 0.f;
            float s1 = ((mem1 - 1.0f) > 0.f) ? 1.f : 0.f;
            float2 o2; o2.x = s0; o2.y = s1;
            *(float2*)&out[ob + (size_t)u * (BBs * CCh * NP)] = o2;
            if (s0 != 0.f) mem0 = 0.f;
            if (s1 != 0.f) mem1 = 0.f;
        }
    }
}

// ---------------- TIM conv2 (grouped) + BN + fused LIF2, hoisted indexing, float4 weights ----
// Block per (c, z=br*4+b), loops t with membrane in registers; writes spikes directly.
__global__ __launch_bounds__(256)
void tim_conv2_kernel(const float* __restrict__ sp, const float* __restrict__ wdn,
                      const float* __restrict__ sc, const float* __restrict__ sh,
                      float* __restrict__ out)
{
    __shared__ __align__(16) float4 sW4[360];   // [((t*4+r)*3+dc)*3+dh] = {w0,w1,w2,0}
    __shared__ float sIn[12 * 342];
    int c  = blockIdx.x;
    int z  = blockIdx.y;
    int b  = z & 3;
    int br = z >> 2;
    int tid = threadIdx.x;

    // pack weights: one float4 row per (t,r,dc,dh) tap-row, broadcast-friendly
    if (tid < 90) {
        // each of 90 threads packs 4 rows (360 rows total); row = (t*4+r)*9 + dc*3 + dh
#pragma unroll
        for (int q = 0; q < 4; q++) {
            int row = tid * 4 + q;
            const float* wsrc = &wdn[row * 3];
            sW4[row] = make_float4(wsrc[0], wsrc[1], wsrc[2], 0.f);
        }
    }

    // ---- hoisted staging descriptors (t-invariant; gmem advances by t*stride) ----
    int sOff[16], gOff[16];
#pragma unroll
    for (int j = 0; j < 16; j++) {
        int i = tid + j * 256;
        sOff[j] = -1; gOff[j] = -1;
        if (i < 3888) {
            int pl = i / 324, rem = i % 324;
            int hh = rem / 18, ww = rem % 18;
            int r = pl / 3, dc = pl % 3;
            int ci = c + dc - 1;
            int hy = hh - 1, wx = ww - 1;
            sOff[j] = pl * 342 + hh * 19 + ww;
            if (ci >= 0 && ci < CCh && hy >= 0 && hy < 16 && wx >= 0 && wx < 16)
                gOff[j] = (((br * 40 + r) * BBs + b) * CCh + ci) * NP + hy * 16 + wx;
        }
    }

    int h = tid >> 4, w = tid & 15;
    float mem = 0.f;
    float pf[16];

    // stage t=0
#pragma unroll
    for (int j = 0; j < 16; j++) pf[j] = (gOff[j] >= 0) ? sp[gOff[j]] : 0.f;
#pragma unroll
    for (int j = 0; j < 16; j++) if (sOff[j] >= 0) sIn[sOff[j]] = pf[j];
    __syncthreads();

#pragma unroll 1
    for (int t = 0; t < 10; t++) {
        if (t < 9) {
            const float* spt = sp + (size_t)(t + 1) * (4 * BBs * CCh * NP);
#pragma unroll
            for (int j = 0; j < 16; j++) pf[j] = (gOff[j] >= 0) ? spt[gOff[j]] : 0.f;
        }

        float acc = 0.f;
        const float4* wrow = &sW4[t * 36];
#pragma unroll
        for (int r = 0; r < 4; r++) {
#pragma unroll
            for (int dc = 0; dc < 3; dc++) {
                const float4* wq = &wrow[(r * 3 + dc) * 3];
                const float* pv = &sIn[(r * 3 + dc) * 342];
#pragma unroll
                for (int dh = 0; dh < 3; dh++) {
                    float4 wv = wq[dh];                      // broadcast LDS.128
                    const float* rp = &pv[(h + dh) * 19 + w];
                    acc += rp[0] * wv.x;
                    acc += rp[1] * wv.y;
                    acc += rp[2] * wv.z;
                }
            }
        }
        float yv = acc * sc[t] + sh[t];
        mem = mem + (yv - mem) * 0.5f;
        float spk = ((mem - 1.0f) > 0.f) ? 1.f : 0.f;
        out[(size_t)br * S_TBCN + (((size_t)t * BBs + b) * CCh + c) * NP + tid] = spk;
        if (spk != 0.f) mem = 0.f;

        if (t < 9) {
            __syncthreads();
#pragma unroll
            for (int j = 0; j < 16; j++) if (sOff[j] >= 0) sIn[sOff[j]] = pf[j];
            __syncthreads();
        }
    }
}

// ---------------- LIF variants ----------------
__global__ void lif_kernel(const float* __restrict__ in, float* __restrict__ out,
                           int nChains, int stride, float vth)
{
    int i = blockIdx.x * blockDim.x + threadIdx.x;
    if (i >= nChains) return;
    float mem = 0.f;
    int p = i;
#pragma unroll
    for (int s = 0; s < 10; s++, p += stride) {
        float x = in[p];
        mem = mem + (x - mem) * 0.5f;
        float spk = ((mem - vth) > 0.f) ? 1.f : 0.f;
        out[p] = spk;
        if (spk != 0.f) mem = 0.f;
    }
}

__global__ void lif_resid_kernel(const float* __restrict__ in, const float* __restrict__ res,
                                 float* __restrict__ out, int nChains, int stride, float vth)
{
    int i = blockIdx.x * blockDim.x + threadIdx.x;
    if (i >= nChains) return;
    float mem = 0.f;
    int p = i;
#pragma unroll
    for (int s = 0; s < 10; s++, p += stride) {
        float x = in[p];
        mem = mem + (x - mem) * 0.5f;
        float spk = ((mem - vth) > 0.f) ? 1.f : 0.f;
        out[p] = res[p] + spk;
        if (spk != 0.f) mem = 0.f;
    }
}

// ---------------- KtV: per (t,b,head): 16x16 Gram over N ----------------
__global__ void ktv_kernel(const float* __restrict__ ks, const float* __restrict__ vs,
                           float* __restrict__ ktv)
{
    __shared__ float kT[16 * 257];
    __shared__ float vT[16 * 257];
    int tbh = blockIdx.x;
    int hh = tbh & 15;
    int tb = tbh >> 4;
    size_t base = ((size_t)tb * CCh + hh * 16) * NP;
    int tid = threadIdx.x;
    for (int i = tid; i < 16 * 256; i += 256) {
        int r = i >> 8, n = i & 255;
        kT[r * 257 + n] = ks[base + (size_t)r * NP + n];
        vT[r * 257 + n] = vs[base + (size_t)r * NP + n];
    }
    __syncthreads();
    int dd = tid >> 4, de = tid & 15;
    const float* kr = &kT[dd * 257];
    const float* vr = &vT[de * 257];
    float acc = 0.f;
#pragma unroll 8
    for (int n = 0; n < 256; n++) acc += kr[n] * vr[n];
    ktv[(size_t)tbh * 256 + dd * 16 + de] = acc;
}

// ---------------- attn out: o = 0.25 * Q (KtV) ----------------
__global__ void attn_o_kernel(const float* __restrict__ qs, const float* __restrict__ ktv,
                              float* __restrict__ o)
{
    __shared__ float sK[256];
    int tbh = blockIdx.x;
    int hh = tbh & 15;
    int tb = tbh >> 4;
    int tid = threadIdx.x;
    sK[tid] = ktv[(size_t)tbh * 256 + tid];
    __syncthreads();
    size_t base = ((size_t)tb * CCh + hh * 16) * NP + tid;
    float q[16];
#pragma unroll
    for (int d = 0; d < 16; d++) q[d] = qs[base + (size_t)d * NP];
#pragma unroll
    for (int dp = 0; dp < 16; dp++) {
        float acc = 0.f;
#pragma unroll
        for (int d = 0; d < 16; d++) acc += q[d] * sK[d * 16 + dp];
        o[base + (size_t)dp * NP] = acc * 0.25f;
    }
}

// ---------------- orchestration ----------------
extern "C" void kernel_launch(void* const* d_in, const int* in_sizes, int n_in,
                              void* d_out, int out_size)
{
    (void)in_sizes; (void)n_in; (void)out_size;
    const float* x        = (const float*)d_in[0];
    const float* q_w      = (const float*)d_in[1];
    const float* q_bn     = (const float*)d_in[2];
    const float* k_w      = (const float*)d_in[3];
    const float* k_bn     = (const float*)d_in[4];
    const float* v_w      = (const float*)d_in[5];
    const float* v_bn     = (const float*)d_in[6];
    const float* proj_w   = (const float*)d_in[7];
    const float* proj_bn  = (const float*)d_in[8];
    const float* tim_up_w = (const float*)d_in[9];
    const float* tim_bn1  = (const float*)d_in[10];
    const float* tim_dn_w = (const float*)d_in[11];
    const float* tim_bn2  = (const float*)d_in[12];
    const float* fc1_w    = (const float*)d_in[13];
    const float* fc1_b    = (const float*)d_in[14];
    const float* fc1_bn   = (const float*)d_in[15];
    const float* fc2_w    = (const float*)d_in[16];
    const float* fc2_b    = (const float*)d_in[17];
    const float* fc2_bn   = (const float*)d_in[18];
    float* outp = (float*)d_out;

    float *bufA, *bufB, *spk1, *spk2, *ybuf, *obuf, *hbuf, *ktvb, *wqkv;
    float *scal, *shif, *t1s, *t1h, *t2s, *t2h;
    cudaGetSymbolAddress((void**)&bufA, g_bufA);
    cudaGetSymbolAddress((void**)&bufB, g_bufB);
    cudaGetSymbolAddress((void**)&spk1, g_spk1);
    cudaGetSymbolAddress((void**)&spk2, g_spk2);
    cudaGetSymbolAddress((void**)&ybuf, g_y);
    cudaGetSymbolAddress((void**)&obuf, g_o);
    cudaGetSymbolAddress((void**)&hbuf, g_h);
    cudaGetSymbolAddress((void**)&ktvb, g_ktv);
    cudaGetSymbolAddress((void**)&wqkv, g_wqkv);
    cudaGetSymbolAddress((void**)&scal, g_scale);
    cudaGetSymbolAddress((void**)&shif, g_shift);
    cudaGetSymbolAddress((void**)&t1s,  g_t1s);
    cudaGetSymbolAddress((void**)&t1h,  g_t1h);
    cudaGetSymbolAddress((void**)&t2s,  g_t2s);
    cudaGetSymbolAddress((void**)&t2h,  g_t2h);

    // all setup in one launch: wqkv concat + every BN fold
    prep_all_kernel<<<779, 256>>>(q_w, k_w, v_w, wqkv,
                                  q_bn, k_bn, v_bn, proj_bn,
                                  fc1_bn, fc1_b, fc2_bn, fc2_b,
                                  tim_bn1, tim_bn2,
                                  scal, shif, t1s, t1h, t2s, t2h);

    // merged q/k/v GEMM: Out (tb, 768, n)
    gemm_bn_kernel<<<dim3(6, 2, TT*BBs), 256>>>(x, wqkv, bufA, 768, CCh,
                                                scal + SC_QKV, shif + SC_QKV);

    // TIM: conv1+BN+LIF1 (all branches), conv2+BN+LIF2 fused
    tim_conv1_kernel<<<dim3(CCh, BBs, 3), 256>>>(bufA, tim_up_w, t1s, t1h, spk1);
    tim_conv2_kernel<<<dim3(CCh, 12), 256>>>(spk1, tim_dn_w, t2s, t2h, spk2);

    // attention (linear, binary, exact): q=br0, k=br1, v=br2
    ktv_kernel<<<TT*BBs*16, 256>>>(spk2 + S_TBCN, spk2 + 2*S_TBCN, ktvb);
    attn_o_kernel<<<TT*BBs*16, 256>>>(spk2, ktvb, obuf);
    lif_kernel<<<(BCN + 255)/256, 256>>>(obuf, obuf, BCN, BCN, 0.5f);

    // projection + BN + lif; residual h = x + spikes
    gemm_bn_kernel<<<dim3(2, 2, TT*BBs), 256>>>(obuf, proj_w, ybuf, CCh, CCh,
                                                scal + SC_PROJ, shif + SC_PROJ);
    lif_resid_kernel<<<(BCN + 255)/256, 256>>>(ybuf, x, hbuf, BCN, BCN, 1.0f);

    // MLP
    gemm_bn_kernel<<<dim3(8, 2, TT*BBs), 256>>>(hbuf, fc1_w, bufA, HIDD, CCh,
                                                scal + SC_FC1, shif + SC_FC1);
    lif_kernel<<<(BHN + 255)/256, 256>>>(bufA, bufB, BHN, BHN, 1.0f);

    gemm_bn_kernel<<<dim3(2, 2, TT*BBs), 256>>>(bufB, fc2_w, ybuf, CCh, HIDD,
                                                scal + SC_FC2, shif + SC_FC2);
    lif_resid_kernel<<<(BCN + 255)/256, 256>>>(ybuf, hbuf, outp, BCN, BCN, 1.0f);
}